// round 1
// baseline (speedup 1.0000x reference)
#include <cuda_runtime.h>

#define Nn 8192
#define Dd 1024
#define BATCH 32

// Persistent scratch (no allocations allowed).
__device__ float g_R[7][BATCH][Dd];    // h @ Wr_m(k).T for k=0..6
__device__ float g_sc[BATCH][Nn];      // concatenated skips: column block p = skips[p]
__device__ float g_acc[BATCH][Dd];     // current layer pre-activation accumulator

// ---------------------------------------------------------------------------
// Generic masked matvec block:
//   out[b, d0+d] += sum_{n in [n0,n1)} X[b,n] * W[d0+d, n] * (adjA[n*Nn + d0+d] != 0)
// Block = 256 threads, d-tile = 64, n processed in 64-wide subtiles.
// Inner loop is FFMA-bound: per nq-step/warp: 1 LDS.128 (h) + 8 LDS.128 bcast (w)
// + 32 FFMA  ->  ~64 FMA/cyc/SM (fp32 pipe peak).
// ---------------------------------------------------------------------------
__device__ __forceinline__ void mv_block(
    const float* __restrict__ W, int wstride,
    const int* __restrict__ adjA,          // adj + rowoff*Nn + colbase
    const float* __restrict__ X, int xstride,
    float* __restrict__ out,               // [32][1024], atomicAdd
    int d0, int n0, int n1)
{
    __shared__ int    adjs[64][65];        // [n][d], padded
    __shared__ float  wm[64][64];          // [d][n], premultiplied W*mask
    __shared__ float4 hs[16][33];          // [nq][b] = X[b][4nq..4nq+3], padded

    const int t = threadIdx.x;
    const int warp = t >> 5, lane = t & 31;

    float acc[8];
#pragma unroll
    for (int j = 0; j < 8; j++) acc[j] = 0.f;

    for (int nb = n0; nb < n1; nb += 64) {
        // phase 1: stage adj tile (coalesced over d) and h tile (coalesced over n)
#pragma unroll
        for (int ii = 0; ii < 16; ii++) {
            int idx = ii * 256 + t;
            int n = idx >> 6, d = idx & 63;
            adjs[n][d] = adjA[(size_t)(nb + n) * Nn + d0 + d];
        }
#pragma unroll
        for (int ii = 0; ii < 8; ii++) {
            int idx = ii * 256 + t;
            int b = idx >> 6, n = idx & 63;
            ((float*)hs)[(n >> 2) * 132 + b * 4 + (n & 3)] =
                X[(size_t)b * xstride + nb + n];
        }
        __syncthreads();

        // phase 2: premultiply mask into smem (coalesced W reads over n)
#pragma unroll
        for (int ii = 0; ii < 16; ii++) {
            int idx = ii * 256 + t;
            int d = idx >> 6, n = idx & 63;
            float w = W[(size_t)(d0 + d) * wstride + nb + n];
            wm[d][n] = adjs[n][d] ? w : 0.f;
        }
        __syncthreads();

        // phase 3: FFMA inner loop. lane = batch, warp owns 8 d's.
        const int dbase = warp * 8;
#pragma unroll
        for (int nq = 0; nq < 16; nq++) {
            float4 hv = hs[nq][lane];
#pragma unroll
            for (int j = 0; j < 8; j++) {
                float4 w4 = *(const float4*)&wm[dbase + j][nq * 4];
                acc[j] += hv.x * w4.x;
                acc[j] += hv.y * w4.y;
                acc[j] += hv.z * w4.z;
                acc[j] += hv.w * w4.w;
            }
        }
        __syncthreads();
    }

#pragma unroll
    for (int j = 0; j < 8; j++)
        atomicAdd(&out[lane * Dd + d0 + warp * 8 + j], acc[j]);
}

// ---------------------------------------------------------------------------

__global__ void zero_R_kernel() {
    int idx = blockIdx.x * 256 + threadIdx.x;   // 7*32*1024 = 896*256
    ((float*)g_R)[idx] = 0.f;
}

// R[k] = h @ Wr_m(k).T ; only n >= (k+1)*D contributes (mask zeroes the rest).
__global__ void __launch_bounds__(256) wr_kernel(
    const float* __restrict__ W_r, const int* __restrict__ adj,
    const float* __restrict__ h)
{
    int k = blockIdx.z;
    int n0 = (k + 1 + blockIdx.y) * 1024;
    if (n0 >= Nn) return;
    mv_block(W_r + (size_t)k * Dd * Nn, Nn,
             adj + k * Dd,                 // rowoff 0, colbase k*D
             h, Nn,
             &g_R[k][0][0],
             blockIdx.x * 64, n0, n0 + 1024);
}

// skips[0] = sigmoid(x @ W_in.T + b_in + R[0]); also init acc = b_h[0] + R[1].
__global__ void prelayer_kernel(
    const float* __restrict__ x, const float* __restrict__ W_in,
    const float* __restrict__ b_in, const float* __restrict__ b_h)
{
    int idx = blockIdx.x * 256 + threadIdx.x;  // 32768
    int d = idx & 1023, bt = idx >> 10;
    const float4* xr = (const float4*)(x + bt * 256);
    const float4* wr = (const float4*)(W_in + (size_t)d * 256);
    float s = 0.f;
#pragma unroll 8
    for (int c = 0; c < 64; c++) {
        float4 a = xr[c], b = wr[c];
        s += a.x * b.x + a.y * b.y + a.z * b.z + a.w * b.w;
    }
    s += b_in[d] + g_R[0][bt][d];
    g_sc[bt][d] = 1.f / (1.f + expf(-s));
    g_acc[bt][d] = b_h[d] + g_R[1][bt][d];
}

// Layer i masked matvecs: blockIdx.y < 8 -> Wh part, else Ws (skip) part.
__global__ void __launch_bounds__(256) layer_mv_kernel(
    const float* __restrict__ Wh, const float* __restrict__ Ws,
    const int* __restrict__ adj, int i)
{
    int d0 = blockIdx.x * 64;
    int y = blockIdx.y;
    if (y < 8) {
        // t += xx_i @ Wh_m(i).T : n in [0,1024), rowoff=i*D, colbase=(i+1)*D
        mv_block(Wh, Dd,
                 adj + (size_t)i * Dd * Nn + (i + 1) * Dd,
                 &g_sc[0][0] + i * Dd, Nn,
                 &g_acc[0][0], d0, y * 128, y * 128 + 128);
    } else {
        // t += sc @ Ws_m(i-1).T : c in [0, i*1024), rowoff=0, colbase=(i+1)*D
        int c0 = (y - 8) * 128;
        mv_block(Ws, 6144,
                 adj + (i + 1) * Dd,
                 &g_sc[0][0], Nn,
                 &g_acc[0][0], d0, c0, c0 + 128);
    }
}

// skips[i+1] = sigmoid(acc); init next layer's acc = b_h[i+1] (+ R[i+2] if i<5).
__global__ void sig_init_kernel(const float* __restrict__ b_h, int i) {
    int idx = blockIdx.x * 256 + threadIdx.x;
    int d = idx & 1023, bt = idx >> 10;
    float s = g_acc[bt][d];
    g_sc[bt][(i + 1) * Dd + d] = 1.f / (1.f + expf(-s));
    if (i < 6) {
        float a = b_h[(i + 1) * Dd + d];
        if (i < 5) a += g_R[i + 2][bt][d];
        g_acc[bt][d] = a;
    }
}

// out = skips[7] @ W_o.T + b_o
__global__ void final_kernel(const float* __restrict__ W_o,
                             const float* __restrict__ b_o,
                             float* __restrict__ out)
{
    int idx = blockIdx.x * 256 + threadIdx.x;  // 2048
    int o = idx & 63, bt = idx >> 6;
    const float4* sr = (const float4*)&g_sc[bt][7 * Dd];
    const float4* wr = (const float4*)(W_o + (size_t)o * Dd);
    float s = 0.f;
#pragma unroll 8
    for (int c = 0; c < 256; c++) {
        float4 a = sr[c], b = wr[c];
        s += a.x * b.x + a.y * b.y + a.z * b.z + a.w * b.w;
    }
    out[bt * 64 + o] = s + b_o[o];
}

// ---------------------------------------------------------------------------

extern "C" void kernel_launch(void* const* d_in, const int* in_sizes, int n_in,
                              void* d_out, int out_size)
{
    const float* x    = (const float*)d_in[0];
    const float* h    = (const float*)d_in[1];
    const int*   adj  = (const int*)d_in[2];
    const float* W_in = (const float*)d_in[3];
    const float* b_in = (const float*)d_in[4];
    const float* W_h  = (const float*)d_in[5];
    const float* b_h  = (const float*)d_in[6];
    const float* W_r  = (const float*)d_in[7];
    const float* W_s  = (const float*)d_in[8];
    const float* W_o  = (const float*)d_in[9];
    const float* b_o  = (const float*)d_in[10];
    float* out = (float*)d_out;

    zero_R_kernel<<<896, 256>>>();
    wr_kernel<<<dim3(16, 7, 7), 256>>>(W_r, adj, h);
    prelayer_kernel<<<128, 256>>>(x, W_in, b_in, b_h);

    for (int i = 0; i < 7; i++) {
        int ny = 8 + (i >= 1 ? 8 * i : 0);
        const float* Ws = (i >= 1) ? W_s + (size_t)(i - 1) * Dd * 6144 : nullptr;
        layer_mv_kernel<<<dim3(16, ny), 256>>>(
            W_h + (size_t)i * Dd * Dd, Ws, adj, i);
        sig_init_kernel<<<128, 256>>>(b_h, i);
    }

    final_kernel<<<8, 256>>>(W_o, b_o, out);
}

// round 2
// speedup vs baseline: 1.4826x; 1.4826x over previous
#include <cuda_runtime.h>

#define Nn 8192
#define Dd 1024
#define BATCH 32

// Persistent scratch (no allocations allowed).
__device__ float g_R[7][BATCH][Dd];    // h @ Wr_m(k).T for k=0..6
__device__ float g_sc[BATCH][Nn];      // concatenated skips: column block p = skips[p]
__device__ float g_acc[BATCH][Dd];     // current layer pre-activation accumulator

// ---------------------------------------------------------------------------
// Masked matvec block, software-pipelined:
//   out[b, d0+d] += sum_n X[b,n] * W[d0+d, n] * (adjA[n*Nn + d0+d] != 0)
// 256 threads, d-tile 64, n-tile 64, ntiles iterations.
// Per tile: one batched LDG prefetch (adj 16KB + W 16KB + X 8KB) issued
// BEFORE the previous tile's FFMA phase -> DRAM latency hidden by compute.
// ---------------------------------------------------------------------------
__device__ __forceinline__ void mv_block(
    const float* __restrict__ W, int wstride,
    const int* __restrict__ adjA,          // adj + rowoff*Nn + colbase
    const float* __restrict__ X, int xstride,
    float* __restrict__ out,               // [32][1024], atomicAdd
    int d0, int n0, int ntiles)
{
    __shared__ unsigned char adjs[64 * 68];   // [n][d] bytes, 68B row pitch
    __shared__ float  wm[64][64];             // [d][n] premultiplied W*mask
    __shared__ float4 hs[16][33];             // [nq][b]

    const int t    = threadIdx.x;
    const int warp = t >> 5, lane = t & 31;
    const int n4   = t & 15;                  // float4 / int4 column index
    const int drow = t >> 4;                  // 0..15

    float acc[8];
#pragma unroll
    for (int j = 0; j < 8; j++) acc[j] = 0.f;

    int4   a[4];
    float4 w[4];
    float4 xv[2];

    // initial prefetch (tile 0): adj, W, X issued back-to-back (high MLP)
    {
        const int nb = n0;
#pragma unroll
        for (int ii = 0; ii < 4; ii++) {
            int r = ii * 16 + drow;          // = n for adj, = d for W
            a[ii] = *(const int4*)&adjA[(size_t)(nb + r) * Nn + d0 + n4 * 4];
            w[ii] = *(const float4*)&W[(size_t)(d0 + r) * wstride + nb + n4 * 4];
        }
#pragma unroll
        for (int ii = 0; ii < 2; ii++) {
            int b = ii * 16 + drow;
            xv[ii] = *(const float4*)&X[(size_t)b * xstride + nb + n4 * 4];
        }
    }

    for (int tt = 0; tt < ntiles; tt++) {
        __syncthreads();   // previous FFMA phase done reading wm/hs
        // stage adj (as bytes) + X into smem
#pragma unroll
        for (int ii = 0; ii < 4; ii++) {
            int n = ii * 16 + drow;
            uchar4 u = make_uchar4((unsigned char)a[ii].x, (unsigned char)a[ii].y,
                                   (unsigned char)a[ii].z, (unsigned char)a[ii].w);
            *(uchar4*)&adjs[n * 68 + n4 * 4] = u;
        }
#pragma unroll
        for (int ii = 0; ii < 2; ii++) {
            int b = ii * 16 + drow;
            hs[n4][b] = xv[ii];
        }
        __syncthreads();
        // premultiply mask into wm (reads transposed adj from smem)
#pragma unroll
        for (int ii = 0; ii < 4; ii++) {
            int d = ii * 16 + drow;
            float4 wv = w[ii];
            float4 o;
            o.x = adjs[(n4 * 4 + 0) * 68 + d] ? wv.x : 0.f;
            o.y = adjs[(n4 * 4 + 1) * 68 + d] ? wv.y : 0.f;
            o.z = adjs[(n4 * 4 + 2) * 68 + d] ? wv.z : 0.f;
            o.w = adjs[(n4 * 4 + 3) * 68 + d] ? wv.w : 0.f;
            *(float4*)&wm[d][n4 * 4] = o;
        }
        __syncthreads();

        // prefetch NEXT tile while FFMA phase runs
        if (tt + 1 < ntiles) {
            const int nb = n0 + (tt + 1) * 64;
#pragma unroll
            for (int ii = 0; ii < 4; ii++) {
                int r = ii * 16 + drow;
                a[ii] = *(const int4*)&adjA[(size_t)(nb + r) * Nn + d0 + n4 * 4];
                w[ii] = *(const float4*)&W[(size_t)(d0 + r) * wstride + nb + n4 * 4];
            }
#pragma unroll
            for (int ii = 0; ii < 2; ii++) {
                int b = ii * 16 + drow;
                xv[ii] = *(const float4*)&X[(size_t)b * xstride + nb + n4 * 4];
            }
        }

        // FFMA phase: lane = batch, warp owns 8 d's
        const int dbase = warp * 8;
#pragma unroll
        for (int nq = 0; nq < 16; nq++) {
            float4 hv = hs[nq][lane];
#pragma unroll
            for (int j = 0; j < 8; j++) {
                float4 w4 = *(const float4*)&wm[dbase + j][nq * 4];
                acc[j] = fmaf(hv.x, w4.x, acc[j]);
                acc[j] = fmaf(hv.y, w4.y, acc[j]);
                acc[j] = fmaf(hv.z, w4.z, acc[j]);
                acc[j] = fmaf(hv.w, w4.w, acc[j]);
            }
        }
    }

#pragma unroll
    for (int j = 0; j < 8; j++)
        atomicAdd(&out[lane * Dd + d0 + warp * 8 + j], acc[j]);
}

// ---------------------------------------------------------------------------

__global__ void zero_R_kernel() {
    int idx = blockIdx.x * 256 + threadIdx.x;   // 7*32*1024 = 896*256
    ((float*)g_R)[idx] = 0.f;
}

// R[k] = h @ Wr_m(k).T ; only n >= (k+1)*D contributes.
__global__ void __launch_bounds__(256, 2) wr_kernel(
    const float* __restrict__ W_r, const int* __restrict__ adj,
    const float* __restrict__ h)
{
    int k = blockIdx.z;
    int n0 = (k + 1) * 1024 + blockIdx.y * 512;
    if (n0 >= Nn) return;
    mv_block(W_r + (size_t)k * Dd * Nn, Nn,
             adj + k * Dd,
             h, Nn,
             &g_R[k][0][0],
             blockIdx.x * 64, n0, 8);
}

// skips[0] = sigmoid(x @ W_in.T + b_in + R[0]); init acc = b_h[0] + R[1].
__global__ void prelayer_kernel(
    const float* __restrict__ x, const float* __restrict__ W_in,
    const float* __restrict__ b_in, const float* __restrict__ b_h)
{
    int idx = blockIdx.x * 256 + threadIdx.x;  // 32768
    int d = idx & 1023, bt = idx >> 10;
    const float4* xr = (const float4*)(x + bt * 256);
    const float4* wr = (const float4*)(W_in + (size_t)d * 256);
    float s = 0.f;
#pragma unroll 8
    for (int c = 0; c < 64; c++) {
        float4 aa = xr[c], bb = wr[c];
        s += aa.x * bb.x + aa.y * bb.y + aa.z * bb.z + aa.w * bb.w;
    }
    s += b_in[d] + g_R[0][bt][d];
    g_sc[bt][d] = 1.f / (1.f + expf(-s));
    g_acc[bt][d] = b_h[d] + g_R[1][bt][d];
}

// Layer i masked matvecs: blockIdx.y < 16 -> Wh part, else Ws (skip) part.
__global__ void __launch_bounds__(256, 2) layer_mv_kernel(
    const float* __restrict__ Wh, const float* __restrict__ Ws,
    const int* __restrict__ adj, int i)
{
    int d0 = blockIdx.x * 64;
    int y = blockIdx.y;
    if (y < 16) {
        // t += xx_i @ Wh_m(i).T : n in [0,1024), rowoff=i*D, colbase=(i+1)*D
        mv_block(Wh, Dd,
                 adj + (size_t)i * Dd * Nn + (i + 1) * Dd,
                 &g_sc[0][0] + i * Dd, Nn,
                 &g_acc[0][0], d0, (y) * 64, 1);
    } else {
        // t += sc @ Ws_m(i-1).T : c in [0, i*1024), rowoff=0, colbase=(i+1)*D
        mv_block(Ws, 6144,
                 adj + (i + 1) * Dd,
                 &g_sc[0][0], Nn,
                 &g_acc[0][0], d0, (y - 16) * 64, 1);
    }
}

// skips[i+1] = sigmoid(acc); init next layer's acc = b_h[i+1] (+ R[i+2] if i<5).
__global__ void sig_init_kernel(const float* __restrict__ b_h, int i) {
    int idx = blockIdx.x * 256 + threadIdx.x;
    int d = idx & 1023, bt = idx >> 10;
    float s = g_acc[bt][d];
    g_sc[bt][(i + 1) * Dd + d] = 1.f / (1.f + expf(-s));
    if (i < 6) {
        float a = b_h[(i + 1) * Dd + d];
        if (i < 5) a += g_R[i + 2][bt][d];
        g_acc[bt][d] = a;
    }
}

// out = skips[7] @ W_o.T + b_o
__global__ void final_kernel(const float* __restrict__ W_o,
                             const float* __restrict__ b_o,
                             float* __restrict__ out)
{
    int idx = blockIdx.x * 256 + threadIdx.x;  // 2048
    int o = idx & 63, bt = idx >> 6;
    const float4* sr = (const float4*)&g_sc[bt][7 * Dd];
    const float4* wr = (const float4*)(W_o + (size_t)o * Dd);
    float s = 0.f;
#pragma unroll 8
    for (int c = 0; c < 256; c++) {
        float4 aa = sr[c], bb = wr[c];
        s += aa.x * bb.x + aa.y * bb.y + aa.z * bb.z + aa.w * bb.w;
    }
    out[bt * 64 + o] = s + b_o[o];
}

// ---------------------------------------------------------------------------

extern "C" void kernel_launch(void* const* d_in, const int* in_sizes, int n_in,
                              void* d_out, int out_size)
{
    const float* x    = (const float*)d_in[0];
    const float* h    = (const float*)d_in[1];
    const int*   adj  = (const int*)d_in[2];
    const float* W_in = (const float*)d_in[3];
    const float* b_in = (const float*)d_in[4];
    const float* W_h  = (const float*)d_in[5];
    const float* b_h  = (const float*)d_in[6];
    const float* W_r  = (const float*)d_in[7];
    const float* W_s  = (const float*)d_in[8];
    const float* W_o  = (const float*)d_in[9];
    const float* b_o  = (const float*)d_in[10];
    float* out = (float*)d_out;

    zero_R_kernel<<<896, 256>>>();
    wr_kernel<<<dim3(16, 14, 7), 256>>>(W_r, adj, h);
    prelayer_kernel<<<128, 256>>>(x, W_in, b_in, b_h);

    for (int i = 0; i < 7; i++) {
        int ny = 16 + 16 * i;
        const float* Ws = (i >= 1) ? W_s + (size_t)(i - 1) * Dd * 6144 : nullptr;
        layer_mv_kernel<<<dim3(16, ny), 256>>>(
            W_h + (size_t)i * Dd * Dd, Ws, adj, i);
        sig_init_kernel<<<128, 256>>>(b_h, i);
    }

    final_kernel<<<8, 256>>>(W_o, b_o, out);
}

// round 3
// speedup vs baseline: 1.6171x; 1.0907x over previous
#include <cuda_runtime.h>

#define Nn 8192
#define Dd 1024
#define BATCH 32

typedef unsigned long long ull;

// Persistent scratch (no allocations allowed).
__device__ float g_R[7][BATCH][Dd];    // h @ Wr_m(k).T for k=0..6
__device__ float g_sc[BATCH][Nn];      // concatenated skips: column block p = skips[p]
__device__ float g_acc[BATCH][Dd];     // current layer pre-activation accumulator

__device__ __forceinline__ void fma2(ull& d, ull a, ull b) {
    asm("fma.rn.f32x2 %0, %1, %2, %0;" : "+l"(d) : "l"(a), "l"(b));
}

// ---------------------------------------------------------------------------
// Masked matvec block, software-pipelined, f32x2 inner loop:
//   out[b, d0+d] += sum_n X[b,n] * W[d0+d, n] * (adjA[n*Nn + d0+d] != 0)
// 256 threads, d-tile 64, n-tile 64, ntiles iterations.
// Per tile: one batched LDG prefetch (adj+W+X) issued before the previous
// tile's FFMA phase; inner loop = FFMA2 (2 FMA/instr on the fma pipe).
// ---------------------------------------------------------------------------
__device__ __forceinline__ void mv_block(
    const float* __restrict__ W, int wstride,
    const int* __restrict__ adjA,          // adj + rowoff*Nn + colbase
    const float* __restrict__ X, int xstride,
    float* __restrict__ out,               // [32][1024], atomicAdd
    int d0, int n0, int ntiles)
{
    __shared__ unsigned char adjs[64 * 68];   // [n][d] bytes, 68B row pitch
    __shared__ float  wm[64][64];             // [d][n] premultiplied W*mask
    __shared__ float4 hs[16][33];             // [nq][b]

    const int t    = threadIdx.x;
    const int warp = t >> 5, lane = t & 31;
    const int n4   = t & 15;                  // float4 / int4 column index
    const int drow = t >> 4;                  // 0..15

    ull acc2[8];
#pragma unroll
    for (int j = 0; j < 8; j++) acc2[j] = 0ull;

    int4   a[4];
    float4 w[4];
    float4 xv[2];

    // initial prefetch (tile 0): adj, W, X issued back-to-back (high MLP)
    {
        const int nb = n0;
#pragma unroll
        for (int ii = 0; ii < 4; ii++) {
            int r = ii * 16 + drow;          // = n for adj, = d for W
            a[ii] = *(const int4*)&adjA[(size_t)(nb + r) * Nn + d0 + n4 * 4];
            w[ii] = *(const float4*)&W[(size_t)(d0 + r) * wstride + nb + n4 * 4];
        }
#pragma unroll
        for (int ii = 0; ii < 2; ii++) {
            int b = ii * 16 + drow;
            xv[ii] = *(const float4*)&X[(size_t)b * xstride + nb + n4 * 4];
        }
    }

    for (int tt = 0; tt < ntiles; tt++) {
        __syncthreads();   // previous FFMA phase done reading wm/hs
        // stage adj (as bytes) + X into smem
#pragma unroll
        for (int ii = 0; ii < 4; ii++) {
            int n = ii * 16 + drow;
            uchar4 u = make_uchar4((unsigned char)a[ii].x, (unsigned char)a[ii].y,
                                   (unsigned char)a[ii].z, (unsigned char)a[ii].w);
            *(uchar4*)&adjs[n * 68 + n4 * 4] = u;
        }
#pragma unroll
        for (int ii = 0; ii < 2; ii++) {
            int b = ii * 16 + drow;
            hs[n4][b] = xv[ii];
        }
        __syncthreads();
        // premultiply mask into wm (reads transposed adj from smem)
#pragma unroll
        for (int ii = 0; ii < 4; ii++) {
            int d = ii * 16 + drow;
            float4 wv = w[ii];
            float4 o;
            o.x = adjs[(n4 * 4 + 0) * 68 + d] ? wv.x : 0.f;
            o.y = adjs[(n4 * 4 + 1) * 68 + d] ? wv.y : 0.f;
            o.z = adjs[(n4 * 4 + 2) * 68 + d] ? wv.z : 0.f;
            o.w = adjs[(n4 * 4 + 3) * 68 + d] ? wv.w : 0.f;
            *(float4*)&wm[d][n4 * 4] = o;
        }
        __syncthreads();

        // prefetch NEXT tile while FFMA phase runs
        if (tt + 1 < ntiles) {
            const int nb = n0 + (tt + 1) * 64;
#pragma unroll
            for (int ii = 0; ii < 4; ii++) {
                int r = ii * 16 + drow;
                a[ii] = *(const int4*)&adjA[(size_t)(nb + r) * Nn + d0 + n4 * 4];
                w[ii] = *(const float4*)&W[(size_t)(d0 + r) * wstride + nb + n4 * 4];
            }
#pragma unroll
            for (int ii = 0; ii < 2; ii++) {
                int b = ii * 16 + drow;
                xv[ii] = *(const float4*)&X[(size_t)b * xstride + nb + n4 * 4];
            }
        }

        // FFMA2 phase: lane = batch, warp owns 8 d's.
        // float4 = two adjacent-n f32x2 pairs -> packed FMA, no repacking.
        const int dbase = warp * 8;
#pragma unroll
        for (int nq = 0; nq < 16; nq++) {
            ulonglong2 hv = *(const ulonglong2*)&hs[nq][lane];
#pragma unroll
            for (int j = 0; j < 8; j++) {
                ulonglong2 w2 = *(const ulonglong2*)&wm[dbase + j][nq * 4];
                fma2(acc2[j], hv.x, w2.x);
                fma2(acc2[j], hv.y, w2.y);
            }
        }
    }

#pragma unroll
    for (int j = 0; j < 8; j++) {
        float2 f = *(float2*)&acc2[j];
        atomicAdd(&out[lane * Dd + d0 + warp * 8 + j], f.x + f.y);
    }
}

// ---------------------------------------------------------------------------

__global__ void zero_R_kernel() {
    int idx = blockIdx.x * 256 + threadIdx.x;   // 7*32*1024 = 896*256
    ((float*)g_R)[idx] = 0.f;
}

// R[k] = h @ Wr_m(k).T ; only n >= (k+1)*D contributes.
__global__ void __launch_bounds__(256, 2) wr_kernel(
    const float* __restrict__ W_r, const int* __restrict__ adj,
    const float* __restrict__ h)
{
    int k = blockIdx.z;
    int n0 = (k + 1) * 1024 + blockIdx.y * 512;
    if (n0 >= Nn) return;
    mv_block(W_r + (size_t)k * Dd * Nn, Nn,
             adj + k * Dd,
             h, Nn,
             &g_R[k][0][0],
             blockIdx.x * 64, n0, 8);
}

// skips[0] = sigmoid(x @ W_in.T + b_in + R[0]); init acc = b_h[0] + R[1].
__global__ void prelayer_kernel(
    const float* __restrict__ x, const float* __restrict__ W_in,
    const float* __restrict__ b_in, const float* __restrict__ b_h)
{
    int idx = blockIdx.x * 256 + threadIdx.x;  // 32768
    int d = idx & 1023, bt = idx >> 10;
    const float4* xr = (const float4*)(x + bt * 256);
    const float4* wr = (const float4*)(W_in + (size_t)d * 256);
    float s = 0.f;
#pragma unroll 8
    for (int c = 0; c < 64; c++) {
        float4 aa = xr[c], bb = wr[c];
        s += aa.x * bb.x + aa.y * bb.y + aa.z * bb.z + aa.w * bb.w;
    }
    s += b_in[d] + g_R[0][bt][d];
    g_sc[bt][d] = 1.f / (1.f + expf(-s));
    g_acc[bt][d] = b_h[d] + g_R[1][bt][d];
}

// Layer i masked matvecs: blockIdx.y < 4 -> Wh part (n=1024, 4 chunks of 256),
// else Ws (skip) part (c = i*1024, chunks of 256). Each chunk pipelined x4.
__global__ void __launch_bounds__(256, 2) layer_mv_kernel(
    const float* __restrict__ Wh, const float* __restrict__ Ws,
    const int* __restrict__ adj, int i)
{
    int d0 = blockIdx.x * 64;
    int y = blockIdx.y;
    if (y < 4) {
        // t += xx_i @ Wh_m(i).T : n in [0,1024), rowoff=i*D, colbase=(i+1)*D
        mv_block(Wh, Dd,
                 adj + (size_t)i * Dd * Nn + (i + 1) * Dd,
                 &g_sc[0][0] + i * Dd, Nn,
                 &g_acc[0][0], d0, y * 256, 4);
    } else {
        // t += sc @ Ws_m(i-1).T : c in [0, i*1024), rowoff=0, colbase=(i+1)*D
        mv_block(Ws, 6144,
                 adj + (i + 1) * Dd,
                 &g_sc[0][0], Nn,
                 &g_acc[0][0], d0, (y - 4) * 256, 4);
    }
}

// skips[i+1] = sigmoid(acc); init next layer's acc = b_h[i+1] (+ R[i+2] if i<5).
__global__ void sig_init_kernel(const float* __restrict__ b_h, int i) {
    int idx = blockIdx.x * 256 + threadIdx.x;
    int d = idx & 1023, bt = idx >> 10;
    float s = g_acc[bt][d];
    g_sc[bt][(i + 1) * Dd + d] = 1.f / (1.f + expf(-s));
    if (i < 6) {
        float a = b_h[(i + 1) * Dd + d];
        if (i < 5) a += g_R[i + 2][bt][d];
        g_acc[bt][d] = a;
    }
}

// out = skips[7] @ W_o.T + b_o
__global__ void final_kernel(const float* __restrict__ W_o,
                             const float* __restrict__ b_o,
                             float* __restrict__ out)
{
    int idx = blockIdx.x * 256 + threadIdx.x;  // 2048
    int o = idx & 63, bt = idx >> 6;
    const float4* sr = (const float4*)&g_sc[bt][7 * Dd];
    const float4* wr = (const float4*)(W_o + (size_t)o * Dd);
    float s = 0.f;
#pragma unroll 8
    for (int c = 0; c < 256; c++) {
        float4 aa = sr[c], bb = wr[c];
        s += aa.x * bb.x + aa.y * bb.y + aa.z * bb.z + aa.w * bb.w;
    }
    out[bt * 64 + o] = s + b_o[o];
}

// ---------------------------------------------------------------------------

extern "C" void kernel_launch(void* const* d_in, const int* in_sizes, int n_in,
                              void* d_out, int out_size)
{
    const float* x    = (const float*)d_in[0];
    const float* h    = (const float*)d_in[1];
    const int*   adj  = (const int*)d_in[2];
    const float* W_in = (const float*)d_in[3];
    const float* b_in = (const float*)d_in[4];
    const float* W_h  = (const float*)d_in[5];
    const float* b_h  = (const float*)d_in[6];
    const float* W_r  = (const float*)d_in[7];
    const float* W_s  = (const float*)d_in[8];
    const float* W_o  = (const float*)d_in[9];
    const float* b_o  = (const float*)d_in[10];
    float* out = (float*)d_out;

    zero_R_kernel<<<896, 256>>>();
    wr_kernel<<<dim3(16, 14, 7), 256>>>(W_r, adj, h);
    prelayer_kernel<<<128, 256>>>(x, W_in, b_in, b_h);

    for (int i = 0; i < 7; i++) {
        int ny = 4 + 4 * i;
        const float* Ws = (i >= 1) ? W_s + (size_t)(i - 1) * Dd * 6144 : nullptr;
        layer_mv_kernel<<<dim3(16, ny), 256>>>(
            W_h + (size_t)i * Dd * Dd, Ws, adj, i);
        sig_init_kernel<<<128, 256>>>(b_h, i);
    }

    final_kernel<<<8, 256>>>(W_o, b_o, out);
}

// round 4
// speedup vs baseline: 1.8917x; 1.1698x over previous
#include <cuda_runtime.h>

#define Nn 8192
#define Dd 1024
#define BATCH 32

typedef unsigned long long ull;

// Persistent scratch (no allocations allowed).
__device__ float g_acc[7][BATCH][Dd];  // per-layer pre-activation accumulators
__device__ float g_R0[BATCH][Dd];      // h @ Wr_m(0).T
__device__ float g_sc[BATCH][Nn];      // concatenated skips

__device__ __forceinline__ void fma2(ull& d, ull a, ull b) {
    asm("fma.rn.f32x2 %0, %1, %2, %0;" : "+l"(d) : "l"(a), "l"(b));
}
__device__ __forceinline__ void red4(float* p, float a, float b, float c, float d) {
    asm volatile("red.global.add.v4.f32 [%0], {%1,%2,%3,%4};"
                 :: "l"(p), "f"(a), "f"(b), "f"(c), "f"(d) : "memory");
}

// ---------------------------------------------------------------------------
// Masked matvec block:
//   out[b, d0+d] += sum_n X[b,n] * W[d0+d, n-n0?no: n] * (adjA[n*Nn + d0+d]!=0)
// 256 threads, d-tile 64, n-tile 64, ntiles iterations, register prefetch.
// ---------------------------------------------------------------------------
__device__ __forceinline__ void mv_block(
    const float* __restrict__ W, int wstride,
    const int* __restrict__ adjA,          // adj + rowoff*Nn + colbase
    const float* __restrict__ X,           // row stride Nn
    float* __restrict__ out,               // [32][1024]
    int d0, int n0, int ntiles)
{
    __shared__ unsigned char adjs[64 * 68];   // [n][d] bytes
    __shared__ float  wm[64][64];             // [d][n] premultiplied W*mask
    __shared__ float4 hs[16][33];             // [nq][b]

    const int t    = threadIdx.x;
    const int warp = t >> 5, lane = t & 31;
    const int n4   = t & 15;
    const int drow = t >> 4;

    ull acc2[8];
#pragma unroll
    for (int j = 0; j < 8; j++) acc2[j] = 0ull;

    int4   a[4];
    float4 w[4];
    float4 xv[2];

    {   // initial prefetch: adj + W + X back-to-back (high MLP)
        const int nb = n0;
#pragma unroll
        for (int ii = 0; ii < 4; ii++) {
            int r = ii * 16 + drow;
            a[ii] = *(const int4*)&adjA[(size_t)(nb + r) * Nn + d0 + n4 * 4];
            w[ii] = *(const float4*)&W[(size_t)(d0 + r) * wstride + nb + n4 * 4];
        }
#pragma unroll
        for (int ii = 0; ii < 2; ii++) {
            int b = ii * 16 + drow;
            xv[ii] = *(const float4*)&X[(size_t)b * Nn + nb + n4 * 4];
        }
    }

    for (int tt = 0; tt < ntiles; tt++) {
        __syncthreads();
#pragma unroll
        for (int ii = 0; ii < 4; ii++) {
            int n = ii * 16 + drow;
            uchar4 u = make_uchar4((unsigned char)a[ii].x, (unsigned char)a[ii].y,
                                   (unsigned char)a[ii].z, (unsigned char)a[ii].w);
            *(uchar4*)&adjs[n * 68 + n4 * 4] = u;
        }
#pragma unroll
        for (int ii = 0; ii < 2; ii++) {
            int b = ii * 16 + drow;
            hs[n4][b] = xv[ii];
        }
        __syncthreads();
#pragma unroll
        for (int ii = 0; ii < 4; ii++) {
            int d = ii * 16 + drow;
            float4 wv = w[ii];
            float4 o;
            o.x = adjs[(n4 * 4 + 0) * 68 + d] ? wv.x : 0.f;
            o.y = adjs[(n4 * 4 + 1) * 68 + d] ? wv.y : 0.f;
            o.z = adjs[(n4 * 4 + 2) * 68 + d] ? wv.z : 0.f;
            o.w = adjs[(n4 * 4 + 3) * 68 + d] ? wv.w : 0.f;
            *(float4*)&wm[d][n4 * 4] = o;
        }
        __syncthreads();

        if (tt + 1 < ntiles) {    // prefetch next tile during FFMA phase
            const int nb = n0 + (tt + 1) * 64;
#pragma unroll
            for (int ii = 0; ii < 4; ii++) {
                int r = ii * 16 + drow;
                a[ii] = *(const int4*)&adjA[(size_t)(nb + r) * Nn + d0 + n4 * 4];
                w[ii] = *(const float4*)&W[(size_t)(d0 + r) * wstride + nb + n4 * 4];
            }
#pragma unroll
            for (int ii = 0; ii < 2; ii++) {
                int b = ii * 16 + drow;
                xv[ii] = *(const float4*)&X[(size_t)b * Nn + nb + n4 * 4];
            }
        }

        const int dbase = warp * 8;
#pragma unroll
        for (int nq = 0; nq < 16; nq++) {
            ulonglong2 hv = *(const ulonglong2*)&hs[nq][lane];
#pragma unroll
            for (int j = 0; j < 8; j++) {
                ulonglong2 w2 = *(const ulonglong2*)&wm[dbase + j][nq * 4];
                fma2(acc2[j], hv.x, w2.x);
                fma2(acc2[j], hv.y, w2.y);
            }
        }
    }

    float r[8];
#pragma unroll
    for (int j = 0; j < 8; j++) {
        float2 f = *(float2*)&acc2[j];
        r[j] = f.x + f.y;
    }
    float* op = &out[lane * Dd + d0 + warp * 8];
    red4(op,     r[0], r[1], r[2], r[3]);
    red4(op + 4, r[4], r[5], r[6], r[7]);
}

// ---------------------------------------------------------------------------

// acc[i][b][d] = b_h[i][d]; R0 = 0.
__global__ void init_kernel(const float* __restrict__ b_h) {
    int idx = blockIdx.x * 256 + threadIdx.x;      // 1024 blocks -> 262144
    if (idx < 7 * BATCH * Dd) {
        int d = idx & 1023, i = idx >> 15;
        ((float*)g_acc)[idx] = b_h[i * Dd + d];
    } else {
        ((float*)g_R0)[idx - 7 * BATCH * Dd] = 0.f;
    }
}

// R0 = h @ Wr_m(0).T  (n >= 1024). grid (16, 7, 8), ntiles=2.
__global__ void __launch_bounds__(256, 2) r0_kernel(
    const float* __restrict__ W_r, const int* __restrict__ adj,
    const float* __restrict__ h)
{
    mv_block(W_r, Nn, adj, h, &g_R0[0][0],
             blockIdx.x * 64, (1 + blockIdx.y) * 1024 + blockIdx.z * 128, 2);
}

// skips[0] = sigmoid(x @ W_in.T + b_in + R0)
__global__ void prelayer_kernel(
    const float* __restrict__ x, const float* __restrict__ W_in,
    const float* __restrict__ b_in)
{
    int idx = blockIdx.x * 256 + threadIdx.x;  // 32768
    int d = idx & 1023, bt = idx >> 10;
    const float4* xr = (const float4*)(x + bt * 256);
    const float4* wr = (const float4*)(W_in + (size_t)d * 256);
    float s = 0.f;
#pragma unroll 8
    for (int c = 0; c < 64; c++) {
        float4 aa = xr[c], bb = wr[c];
        s += aa.x * bb.x + aa.y * bb.y + aa.z * bb.z + aa.w * bb.w;
    }
    s += b_in[d] + g_R0[bt][d];
    g_sc[bt][d] = 1.f / (1.f + expf(-s));
}

// Fused launch after skips[j] is ready. grid (16, 13-2j, 8), n-chunk 128:
//   y == 0          : acc[j]   += skips[j] @ Wh_m(j).T        (critical path)
//   y in [1, 7-j)   : acc[i]   += skips[j] @ Ws-block(i,j).T  (i = j+y)
//   y in [7-j,13-2j): acc[j]   += h @ Wr_m(j+1).T slice       (R term)
__global__ void __launch_bounds__(256, 2) L_kernel(
    const float* __restrict__ W_h, const float* __restrict__ W_s,
    const float* __restrict__ W_r, const int* __restrict__ adj,
    const float* __restrict__ h, int j)
{
    int d0 = blockIdx.x * 64;
    int y = blockIdx.y, z = blockIdx.z;
    if (y == 0) {
        mv_block(W_h + (size_t)j * Dd * Dd, Dd,
                 adj + (size_t)j * Dd * Nn + (j + 1) * Dd,
                 &g_sc[0][0] + j * Dd,
                 &g_acc[j][0][0], d0, z * 128, 2);
    } else if (y <= 6 - j) {
        int i = j + y;   // target layer j+1..6
        mv_block(W_s + (size_t)(i - 1) * Dd * 6144, 6144,
                 adj + (i + 1) * Dd,
                 &g_sc[0][0],
                 &g_acc[i][0][0], d0, j * 1024 + z * 128, 2);
    } else {
        int u = y - (7 - j);           // 0..5-j
        int k = j + 1;
        mv_block(W_r + (size_t)k * Dd * Nn, Nn,
                 adj + k * Dd,
                 h,
                 &g_acc[j][0][0], d0, (k + 1 + u) * 1024 + z * 128, 2);
    }
}

// skips[j+1] = sigmoid(acc[j])
__global__ void sig_kernel(int j) {
    int idx = blockIdx.x * 256 + threadIdx.x;
    int d = idx & 1023, bt = idx >> 10;
    float s = g_acc[j][bt][d];
    g_sc[bt][(j + 1) * Dd + d] = 1.f / (1.f + expf(-s));
}

// out = skips[7] @ W_o.T + b_o
__global__ void final_kernel(const float* __restrict__ W_o,
                             const float* __restrict__ b_o,
                             float* __restrict__ out)
{
    int idx = blockIdx.x * 256 + threadIdx.x;  // 2048
    int o = idx & 63, bt = idx >> 6;
    const float4* sr = (const float4*)&g_sc[bt][7 * Dd];
    const float4* wr = (const float4*)(W_o + (size_t)o * Dd);
    float s = 0.f;
#pragma unroll 8
    for (int c = 0; c < 256; c++) {
        float4 aa = sr[c], bb = wr[c];
        s += aa.x * bb.x + aa.y * bb.y + aa.z * bb.z + aa.w * bb.w;
    }
    out[bt * 64 + o] = s + b_o[o];
}

// ---------------------------------------------------------------------------

extern "C" void kernel_launch(void* const* d_in, const int* in_sizes, int n_in,
                              void* d_out, int out_size)
{
    const float* x    = (const float*)d_in[0];
    const float* h    = (const float*)d_in[1];
    const int*   adj  = (const int*)d_in[2];
    const float* W_in = (const float*)d_in[3];
    const float* b_in = (const float*)d_in[4];
    const float* W_h  = (const float*)d_in[5];
    const float* b_h  = (const float*)d_in[6];
    const float* W_r  = (const float*)d_in[7];
    const float* W_s  = (const float*)d_in[8];
    const float* W_o  = (const float*)d_in[9];
    const float* b_o  = (const float*)d_in[10];
    float* out = (float*)d_out;

    init_kernel<<<1024, 256>>>(b_h);
    r0_kernel<<<dim3(16, 7, 8), 256>>>(W_r, adj, h);
    prelayer_kernel<<<128, 256>>>(x, W_in, b_in);

    for (int j = 0; j < 7; j++) {
        L_kernel<<<dim3(16, 13 - 2 * j, 8), 256>>>(W_h, W_s, W_r, adj, h, j);
        sig_kernel<<<128, 256>>>(j);
    }

    final_kernel<<<8, 256>>>(W_o, b_o, out);
}